// round 2
// baseline (speedup 1.0000x reference)
#include <cuda_runtime.h>

// Problem constants
#define BATCH 16
#define H 1080
#define W 1920
#define OH (H - 6)   // 1074
#define OW (W - 6)   // 1914

// Tile config
#define TW 32
#define TH 16
#define RW (TW + 6)  // 38
#define RH (TH + 6)  // 22
#define NTHREADS 512

#define C1_CONST 6.5025f    // (0.01*255)^2
#define C2_CONST 58.5225f   // (0.03*255)^2

__device__ double g_acc;

__global__ void zero_acc_kernel() { g_acc = 0.0; }

__global__ __launch_bounds__(NTHREADS) void ssim_kernel(
    const float* __restrict__ img1,
    const float* __restrict__ img2,
    const float* __restrict__ window)
{
    __shared__ float a_s[RH * RW];
    __shared__ float b_s[RH * RW];
    __shared__ float cs1[TH * RW];
    __shared__ float cs2[TH * RW];
    __shared__ float cs11[TH * RW];
    __shared__ float cs22[TH * RW];
    __shared__ float cs12[TH * RW];
    __shared__ float red[NTHREADS / 32];

    const int tilesX = (OW + TW - 1) / TW;  // 60
    const int tilesY = (OH + TH - 1) / TH;  // 68

    int bid = blockIdx.x;
    int batch = bid / (tilesX * tilesY);
    int t = bid % (tilesX * tilesY);
    int ty0 = (t / tilesX) * TH;
    int tx0 = (t % tilesX) * TW;

    const float* p1 = img1 + (size_t)batch * H * W;
    const float* p2 = img2 + (size_t)batch * H * W;

    int tid = threadIdx.x;

    // Phase 1: load input region (clamped at borders; clamped values only feed
    // out-of-range outputs which are discarded)
    for (int i = tid; i < RH * RW; i += NTHREADS) {
        int r = i / RW;
        int c = i - r * RW;
        int gy = ty0 + r; if (gy > H - 1) gy = H - 1;
        int gx = tx0 + c; if (gx > W - 1) gx = W - 1;
        size_t off = (size_t)gy * W + gx;
        a_s[i] = p1[off];
        b_s[i] = p2[off];
    }
    __syncthreads();

    // Phase 2: vertical 7-sums of the 5 quantities
    for (int i = tid; i < TH * RW; i += NTHREADS) {
        int r = i / RW;
        int c = i - r * RW;
        float s1 = 0.f, s2 = 0.f, s11 = 0.f, s22 = 0.f, s12 = 0.f;
        #pragma unroll
        for (int k = 0; k < 7; k++) {
            float a = a_s[(r + k) * RW + c];
            float b = b_s[(r + k) * RW + c];
            s1 += a; s2 += b;
            s11 += a * a; s22 += b * b; s12 += a * b;
        }
        cs1[i] = s1; cs2[i] = s2; cs11[i] = s11; cs22[i] = s22; cs12[i] = s12;
    }
    __syncthreads();

    // Phase 3: horizontal 7-sums + SSIM formula (one output per thread)
    const float inv = window[0];  // 1/49 for the uniform window
    int tx = tid & (TW - 1);
    int tyy = tid / TW;
    int ox = tx0 + tx;
    int oy = ty0 + tyy;
    float val = 0.f;
    if (ox < OW && oy < OH) {
        float s1 = 0.f, s2 = 0.f, s11 = 0.f, s22 = 0.f, s12 = 0.f;
        int base = tyy * RW + tx;
        #pragma unroll
        for (int k = 0; k < 7; k++) {
            s1 += cs1[base + k];
            s2 += cs2[base + k];
            s11 += cs11[base + k];
            s22 += cs22[base + k];
            s12 += cs12[base + k];
        }
        float mu1 = s1 * inv, mu2 = s2 * inv;
        float mu1s = mu1 * mu1, mu2s = mu2 * mu2, mu12 = mu1 * mu2;
        float sig1 = s11 * inv - mu1s;
        float sig2 = s22 * inv - mu2s;
        float sig12 = s12 * inv - mu12;
        float v1 = 2.f * sig12 + C2_CONST;
        float v2 = sig1 + sig2 + C2_CONST;
        val = (2.f * mu12 + C1_CONST) * v1 / ((mu1s + mu2s + C1_CONST) * v2);
    }

    // Block reduction (512 -> 16 -> 1), then one double atomic per block
    int lane = tid & 31;
    int warp = tid >> 5;
    #pragma unroll
    for (int off = 16; off; off >>= 1)
        val += __shfl_down_sync(0xffffffff, val, off);
    if (lane == 0) red[warp] = val;
    __syncthreads();
    if (warp == 0) {
        float v = (lane < NTHREADS / 32) ? red[lane] : 0.f;
        #pragma unroll
        for (int off = 8; off; off >>= 1)
            v += __shfl_down_sync(0xffffffff, v, off);
        if (lane == 0)
            atomicAdd(&g_acc, (double)v);
    }
}

__global__ void finalize_kernel(float* out) {
    out[0] = (float)(g_acc / ((double)BATCH * OH * OW));
}

extern "C" void kernel_launch(void* const* d_in, const int* in_sizes, int n_in,
                              void* d_out, int out_size) {
    const float* img1 = (const float*)d_in[0];
    const float* img2 = (const float*)d_in[1];
    const float* window = (const float*)d_in[2];
    float* out = (float*)d_out;

    const int tilesX = (OW + TW - 1) / TW;  // 60
    const int tilesY = (OH + TH - 1) / TH;  // 68
    int nblocks = BATCH * tilesX * tilesY;  // 65280

    zero_acc_kernel<<<1, 1>>>();
    ssim_kernel<<<nblocks, NTHREADS>>>(img1, img2, window);
    finalize_kernel<<<1, 1>>>(out);
}

// round 3
// speedup vs baseline: 1.3446x; 1.3446x over previous
#include <cuda_runtime.h>

// Problem constants
#define BATCH 16
#define H 1080
#define W 1920
#define OH (H - 6)   // 1074
#define OW (W - 6)   // 1914

// Tile config: each CTA = 256 output columns x 64 output rows, row-streaming.
#define NTHREADS 256
#define TW 256
#define TH 64
#define RW (TW + 6)   // 262 input columns
#define RH (TH + 6)   // 70 input rows (multiple of 7)
#define TILESX 8      // ceil(1914/256)
#define TILESY 17     // ceil(1074/64)

#define C1_CONST 6.5025f    // (0.01*255)^2
#define C2_CONST 58.5225f   // (0.03*255)^2

__device__ double g_acc;

__global__ void zero_acc_kernel() { g_acc = 0.0; }

__global__ __launch_bounds__(NTHREADS) void ssim_kernel(
    const float* __restrict__ img1,
    const float* __restrict__ img2,
    const float* __restrict__ window)
{
    __shared__ float a_row[2][RW];
    __shared__ float b_row[2][RW];
    __shared__ float red[NTHREADS / 32];

    const int bid = blockIdx.x;
    const int batch = bid / (TILESX * TILESY);
    const int tidx = bid % (TILESX * TILESY);
    const int tx0 = (tidx % TILESX) * TW;
    const int ty0 = (tidx / TILESX) * TH;

    const float* __restrict__ p1 = img1 + (size_t)batch * H * W;
    const float* __restrict__ p2 = img2 + (size_t)batch * H * W;

    const int t = threadIdx.x;
    const int ox = tx0 + t;
    const bool colvalid = (ox < OW);
    const float inv = window[0];   // 1/49 for the uniform window

    // Row loader: stage global row (ty0 + r) into buffer `buf`, clamped.
    // Clamped rows/cols only feed outputs that are discarded.
    auto load_row = [&](int r, int buf) {
        int gy = ty0 + r; if (gy > H - 1) gy = H - 1;
        const float* r1 = p1 + (size_t)gy * W;
        const float* r2 = p2 + (size_t)gy * W;
        int gx = tx0 + t; if (gx > W - 1) gx = W - 1;
        a_row[buf][t] = r1[gx];
        b_row[buf][t] = r2[gx];
        if (t < RW - NTHREADS) {
            int gx2 = tx0 + t + NTHREADS; if (gx2 > W - 1) gx2 = W - 1;
            a_row[buf][t + NTHREADS] = r1[gx2];
            b_row[buf][t + NTHREADS] = r2[gx2];
        }
    };

    // Register ring buffers for the last 7 rows of horizontal sums.
    float h1[7], h2[7], h11[7], h22[7], h12[7];
    #pragma unroll
    for (int j = 0; j < 7; j++) { h1[j]=0.f; h2[j]=0.f; h11[j]=0.f; h22[j]=0.f; h12[j]=0.f; }
    // Running vertical sums over the 7-row window.
    float v1 = 0.f, v2 = 0.f, v11 = 0.f, v22 = 0.f, v12 = 0.f;
    float acc = 0.f;

    load_row(0, 0);
    __syncthreads();

    for (int rr = 0; rr < RH / 7; rr++) {
        #pragma unroll
        for (int j = 0; j < 7; j++) {
            const int r = rr * 7 + j;
            const int cur = r & 1;
            const int nxt = cur ^ 1;

            // Prefetch next row into the other buffer.
            load_row(r + 1, nxt);

            // Horizontal 7-sums for this thread's column window.
            float s1 = 0.f, s2 = 0.f, s11 = 0.f, s22 = 0.f, s12 = 0.f;
            #pragma unroll
            for (int k = 0; k < 7; k++) {
                float a = a_row[cur][t + k];
                float b = b_row[cur][t + k];
                s1 += a;
                s2 += b;
                s11 = fmaf(a, a, s11);
                s22 = fmaf(b, b, s22);
                s12 = fmaf(a, b, s12);
            }

            // Slide the vertical window: drop row r-7 (slot j), add row r.
            v1  += s1  - h1[j];   h1[j]  = s1;
            v2  += s2  - h2[j];   h2[j]  = s2;
            v11 += s11 - h11[j];  h11[j] = s11;
            v22 += s22 - h22[j];  h22[j] = s22;
            v12 += s12 - h12[j];  h12[j] = s12;

            if (r >= 6) {
                const int oy = ty0 + r - 6;
                if (colvalid && oy < OH) {
                    float mu1 = v1 * inv, mu2 = v2 * inv;
                    float mu1s = mu1 * mu1, mu2s = mu2 * mu2, mu12 = mu1 * mu2;
                    float sig1 = v11 * inv - mu1s;
                    float sig2 = v22 * inv - mu2s;
                    float sg12 = v12 * inv - mu12;
                    float num = (2.f * mu12 + C1_CONST) * (2.f * sg12 + C2_CONST);
                    float den = (mu1s + mu2s + C1_CONST) * (sig1 + sig2 + C2_CONST);
                    acc += num / den;
                }
            }
            __syncthreads();
        }
    }

    // Block reduction (256 -> 8 -> 1), one double atomic per block.
    int lane = t & 31;
    int warp = t >> 5;
    #pragma unroll
    for (int off = 16; off; off >>= 1)
        acc += __shfl_down_sync(0xffffffff, acc, off);
    if (lane == 0) red[warp] = acc;
    __syncthreads();
    if (warp == 0) {
        float v = (lane < NTHREADS / 32) ? red[lane] : 0.f;
        #pragma unroll
        for (int off = 4; off; off >>= 1)
            v += __shfl_down_sync(0xffffffff, v, off);
        if (lane == 0)
            atomicAdd(&g_acc, (double)v);
    }
}

__global__ void finalize_kernel(float* out) {
    out[0] = (float)(g_acc / ((double)BATCH * OH * OW));
}

extern "C" void kernel_launch(void* const* d_in, const int* in_sizes, int n_in,
                              void* d_out, int out_size) {
    const float* img1 = (const float*)d_in[0];
    const float* img2 = (const float*)d_in[1];
    const float* window = (const float*)d_in[2];
    float* out = (float*)d_out;

    int nblocks = BATCH * TILESX * TILESY;  // 2176

    zero_acc_kernel<<<1, 1>>>();
    ssim_kernel<<<nblocks, NTHREADS>>>(img1, img2, window);
    finalize_kernel<<<1, 1>>>(out);
}

// round 4
// speedup vs baseline: 1.9541x; 1.4533x over previous
#include <cuda_runtime.h>

// Problem constants
#define BATCH 16
#define H 1080
#define W 1920
#define OH (H - 6)   // 1074
#define OW (W - 6)   // 1914

// Tiling: CTA = 256 threads, each thread owns 1 output column x TH output rows.
#define NTHREADS 256
#define TW 256
#define TH 120
#define RH (TH + 6)   // 126 input rows (multiple of 7)
#define TILESX 8      // 8*256 = 2048 >= 1914
#define TILESY 9      // 9*120 = 1080 >= 1074
#define NBLOCKS (BATCH * TILESX * TILESY)  // 1152

#define C1_CONST 6.5025f    // (0.01*255)^2
#define C2_CONST 58.5225f   // (0.03*255)^2

__device__ float g_part[NBLOCKS];
__device__ unsigned int g_count = 0;

__global__ __launch_bounds__(NTHREADS) void ssim_kernel(
    const float* __restrict__ img1,
    const float* __restrict__ img2,
    const float* __restrict__ window,
    float* __restrict__ out)
{
    __shared__ float red[NTHREADS / 32];
    __shared__ double redd[NTHREADS / 32];
    __shared__ bool is_last;

    const int bid = blockIdx.x;
    const int batch = bid / (TILESX * TILESY);
    const int tidx = bid % (TILESX * TILESY);
    const int tx0 = (tidx % TILESX) * TW;
    const int ty0 = (tidx / TILESX) * TH;

    const float* __restrict__ p1 = img1 + (size_t)batch * (H * W);
    const float* __restrict__ p2 = img2 + (size_t)batch * (H * W);

    const int t = threadIdx.x;
    const int ox = tx0 + t;
    const bool colvalid = (ox < OW);
    // For invalid columns, clamp the 7-wide read window fully in-bounds;
    // their results are discarded.
    const int oxe = colvalid ? ox : (W - 7);
    const float inv = window[0];   // 1/49 for the uniform window

    // Register ring buffers: horizontal 7-sums of the last 7 rows.
    float h1[7], h2[7], h11[7], h22[7], h12[7];
    #pragma unroll
    for (int j = 0; j < 7; j++) { h1[j]=0.f; h2[j]=0.f; h11[j]=0.f; h22[j]=0.f; h12[j]=0.f; }
    float v1 = 0.f, v2 = 0.f, v11 = 0.f, v22 = 0.f, v12 = 0.f;
    float acc = 0.f;

    for (int rr = 0; rr < RH / 7; rr++) {
        #pragma unroll
        for (int j = 0; j < 7; j++) {
            const int r = rr * 7 + j;
            int gy = ty0 + r; if (gy > H - 1) gy = H - 1;
            const float* __restrict__ r1 = p1 + (size_t)gy * W + oxe;
            const float* __restrict__ r2 = p2 + (size_t)gy * W + oxe;

            // Horizontal 7-sums straight from global (L1-resident lines).
            float s1 = 0.f, s2 = 0.f, s11 = 0.f, s22 = 0.f, s12 = 0.f;
            #pragma unroll
            for (int k = 0; k < 7; k++) {
                float a = __ldg(r1 + k);
                float b = __ldg(r2 + k);
                s1 += a;
                s2 += b;
                s11 = fmaf(a, a, s11);
                s22 = fmaf(b, b, s22);
                s12 = fmaf(a, b, s12);
            }

            // Vertical sliding window: drop row r-7, add row r.
            v1  += s1  - h1[j];   h1[j]  = s1;
            v2  += s2  - h2[j];   h2[j]  = s2;
            v11 += s11 - h11[j];  h11[j] = s11;
            v22 += s22 - h22[j];  h22[j] = s22;
            v12 += s12 - h12[j];  h12[j] = s12;

            if (r >= 6) {
                const int oy = ty0 + r - 6;
                if (colvalid && oy < OH) {
                    float mu1 = v1 * inv, mu2 = v2 * inv;
                    float mu1s = mu1 * mu1, mu2s = mu2 * mu2, mu12 = mu1 * mu2;
                    float sig1 = v11 * inv - mu1s;
                    float sig2 = v22 * inv - mu2s;
                    float sg12 = v12 * inv - mu12;
                    float num = (2.f * mu12 + C1_CONST) * (2.f * sg12 + C2_CONST);
                    float den = (mu1s + mu2s + C1_CONST) * (sig1 + sig2 + C2_CONST);
                    acc += __fdividef(num, den);
                }
            }
        }
    }

    // Block reduction of acc (float; per-block partial magnitude ~3e4).
    int lane = t & 31;
    int warp = t >> 5;
    #pragma unroll
    for (int off = 16; off; off >>= 1)
        acc += __shfl_down_sync(0xffffffff, acc, off);
    if (lane == 0) red[warp] = acc;
    __syncthreads();
    float blockAcc = 0.f;
    if (warp == 0) {
        float v = (lane < NTHREADS / 32) ? red[lane] : 0.f;
        #pragma unroll
        for (int off = 4; off; off >>= 1)
            v += __shfl_down_sync(0xffffffff, v, off);
        blockAcc = v;
    }

    // Last-block-done final reduction (threadfence reduction pattern).
    if (t == 0) {
        g_part[bid] = blockAcc;
        __threadfence();
        unsigned int prev = atomicAdd(&g_count, 1u);
        is_last = (prev == (unsigned int)(gridDim.x - 1));
    }
    __syncthreads();

    if (is_last) {
        double s = 0.0;
        for (int i = t; i < NBLOCKS; i += NTHREADS)
            s += (double)g_part[i];
        #pragma unroll
        for (int off = 16; off; off >>= 1)
            s += __shfl_down_sync(0xffffffff, s, off);
        if (lane == 0) redd[warp] = s;
        __syncthreads();
        if (warp == 0) {
            double v = (lane < NTHREADS / 32) ? redd[lane] : 0.0;
            #pragma unroll
            for (int off = 4; off; off >>= 1)
                v += __shfl_down_sync(0xffffffff, v, off);
            if (lane == 0) {
                out[0] = (float)(v / ((double)BATCH * OH * OW));
                g_count = 0;  // self-reset for next graph replay
            }
        }
    }
}

extern "C" void kernel_launch(void* const* d_in, const int* in_sizes, int n_in,
                              void* d_out, int out_size) {
    const float* img1 = (const float*)d_in[0];
    const float* img2 = (const float*)d_in[1];
    const float* window = (const float*)d_in[2];
    float* out = (float*)d_out;

    ssim_kernel<<<NBLOCKS, NTHREADS>>>(img1, img2, window, out);
}

// round 5
// speedup vs baseline: 2.1405x; 1.0954x over previous
#include <cuda_runtime.h>
#include <cstdint>

// Problem constants
#define BATCH 16
#define H 1080
#define W 1920
#define OH (H - 6)   // 1074
#define OW (W - 6)   // 1914

// Tiling: CTA = 256 threads, each thread owns 1 output column x TH output rows.
#define NTHREADS 256
#define TW 256
#define TH 64
#define RH (TH + 6)   // 70 input rows (multiple of 7)
#define TILESX 8      // 8*256 = 2048 >= 1914
#define TILESY 17     // 17*64 = 1088 >= 1074
#define NBLOCKS (BATCH * TILESX * TILESY)  // 2176

#define C1_CONST 6.5025f    // (0.01*255)^2
#define C2_CONST 58.5225f   // (0.03*255)^2

__device__ float g_part[NBLOCKS];
__device__ unsigned int g_count = 0;

// ---- f32x2 packed helpers (sm_103a) ----
__device__ __forceinline__ unsigned long long pk(float lo, float hi) {
    unsigned long long r;
    asm("mov.b64 %0, {%1, %2};" : "=l"(r) : "f"(lo), "f"(hi));
    return r;
}
__device__ __forceinline__ void unpk(float& lo, float& hi, unsigned long long v) {
    asm("mov.b64 {%0, %1}, %2;" : "=f"(lo), "=f"(hi) : "l"(v));
}
__device__ __forceinline__ unsigned long long add2(unsigned long long a, unsigned long long b) {
    unsigned long long r;
    asm("add.rn.f32x2 %0, %1, %2;" : "=l"(r) : "l"(a), "l"(b));
    return r;
}
__device__ __forceinline__ unsigned long long fma2(unsigned long long a, unsigned long long b,
                                                   unsigned long long c) {
    unsigned long long r;
    asm("fma.rn.f32x2 %0, %1, %2, %3;" : "=l"(r) : "l"(a), "l"(b), "l"(c));
    return r;
}

__global__ __launch_bounds__(NTHREADS) void ssim_kernel(
    const float* __restrict__ img1,
    const float* __restrict__ img2,
    const float* __restrict__ window,
    float* __restrict__ out)
{
    // Per-thread private ring buffers in smem ([j][tid] -> conflict-free, no barriers).
    __shared__ unsigned long long ringAB[7][NTHREADS];  // {s1, s2}
    __shared__ unsigned long long ringSQ[7][NTHREADS];  // {s11, s22}
    __shared__ float              ring12[7][NTHREADS];  // s12
    __shared__ float  red[NTHREADS / 32];
    __shared__ double redd[NTHREADS / 32];
    __shared__ bool   is_last;

    const int bid = blockIdx.x;
    const int batch = bid / (TILESX * TILESY);
    const int tidx = bid % (TILESX * TILESY);
    const int tx0 = (tidx % TILESX) * TW;
    const int ty0 = (tidx / TILESX) * TH;

    const float* __restrict__ p1 = img1 + (size_t)batch * (H * W);
    const float* __restrict__ p2 = img2 + (size_t)batch * (H * W);

    const int t = threadIdx.x;
    const int ox = tx0 + t;
    const bool colvalid = (ox < OW);
    const int oxe = colvalid ? ox : (W - 7);   // clamp window in-bounds; result discarded
    const float inv = window[0];               // 1/49 for the uniform window

    // Zero this thread's ring slots.
    #pragma unroll
    for (int j = 0; j < 7; j++) {
        ringAB[j][t] = 0ull; ringSQ[j][t] = 0ull; ring12[j][t] = 0.f;
    }

    const unsigned long long NEG1 = pk(-1.0f, -1.0f);
    unsigned long long vAB = 0ull, vSQ = 0ull;
    float v12 = 0.f;
    float acc = 0.f;

    for (int rr = 0; rr < RH / 7; rr++) {
        #pragma unroll
        for (int j = 0; j < 7; j++) {
            const int r = rr * 7 + j;
            int gy = ty0 + r; if (gy > H - 1) gy = H - 1;
            const float* __restrict__ r1 = p1 + (size_t)gy * W + oxe;
            const float* __restrict__ r2 = p2 + (size_t)gy * W + oxe;

            float a[7], b[7];
            #pragma unroll
            for (int k = 0; k < 7; k++) { a[k] = __ldg(r1 + k); b[k] = __ldg(r2 + k); }

            // Horizontal 7-sums, image-pair packed: {s1,s2} and {s11,s22}.
            unsigned long long ab0 = pk(a[0], b[0]);
            unsigned long long sAB = ab0;
            unsigned long long sSQ = fma2(ab0, ab0, 0ull);
            float s12 = a[0] * b[0];
            #pragma unroll
            for (int k = 1; k < 7; k++) {
                unsigned long long abk = pk(a[k], b[k]);
                sAB = add2(sAB, abk);
                sSQ = fma2(abk, abk, sSQ);
                s12 = fmaf(a[k], b[k], s12);
            }

            // Vertical sliding window: v += s_new - s_old (packed).
            unsigned long long oAB = ringAB[j][t];
            unsigned long long oSQ = ringSQ[j][t];
            float o12 = ring12[j][t];
            vAB = add2(vAB, fma2(oAB, NEG1, sAB));
            vSQ = add2(vSQ, fma2(oSQ, NEG1, sSQ));
            v12 += s12 - o12;
            ringAB[j][t] = sAB;
            ringSQ[j][t] = sSQ;
            ring12[j][t] = s12;

            if (r >= 6) {
                const int oy = ty0 + r - 6;
                if (colvalid && oy < OH) {
                    float V1, V2, V11, V22;
                    unpk(V1, V2, vAB);
                    unpk(V11, V22, vSQ);
                    float mu1 = V1 * inv, mu2 = V2 * inv;
                    float mu1s = mu1 * mu1, mu2s = mu2 * mu2, mu12 = mu1 * mu2;
                    float sig1 = V11 * inv - mu1s;
                    float sig2 = V22 * inv - mu2s;
                    float sg12 = v12 * inv - mu12;
                    float num = (2.f * mu12 + C1_CONST) * (2.f * sg12 + C2_CONST);
                    float den = (mu1s + mu2s + C1_CONST) * (sig1 + sig2 + C2_CONST);
                    acc += __fdividef(num, den);
                }
            }
        }
    }

    // Block reduction.
    int lane = t & 31;
    int warp = t >> 5;
    #pragma unroll
    for (int off = 16; off; off >>= 1)
        acc += __shfl_down_sync(0xffffffff, acc, off);
    if (lane == 0) red[warp] = acc;
    __syncthreads();
    float blockAcc = 0.f;
    if (warp == 0) {
        float v = (lane < NTHREADS / 32) ? red[lane] : 0.f;
        #pragma unroll
        for (int off = 4; off; off >>= 1)
            v += __shfl_down_sync(0xffffffff, v, off);
        blockAcc = v;
    }

    // Last-block final reduction.
    if (t == 0) {
        g_part[bid] = blockAcc;
        __threadfence();
        unsigned int prev = atomicAdd(&g_count, 1u);
        is_last = (prev == (unsigned int)(gridDim.x - 1));
    }
    __syncthreads();

    if (is_last) {
        double s = 0.0;
        for (int i = t; i < NBLOCKS; i += NTHREADS)
            s += (double)g_part[i];
        #pragma unroll
        for (int off = 16; off; off >>= 1)
            s += __shfl_down_sync(0xffffffff, s, off);
        if (lane == 0) redd[warp] = s;
        __syncthreads();
        if (warp == 0) {
            double v = (lane < NTHREADS / 32) ? redd[lane] : 0.0;
            #pragma unroll
            for (int off = 4; off; off >>= 1)
                v += __shfl_down_sync(0xffffffff, v, off);
            if (lane == 0) {
                out[0] = (float)(v / ((double)BATCH * OH * OW));
                g_count = 0;  // self-reset for next graph replay
            }
        }
    }
}

extern "C" void kernel_launch(void* const* d_in, const int* in_sizes, int n_in,
                              void* d_out, int out_size) {
    const float* img1 = (const float*)d_in[0];
    const float* img2 = (const float*)d_in[1];
    const float* window = (const float*)d_in[2];
    float* out = (float*)d_out;

    ssim_kernel<<<NBLOCKS, NTHREADS>>>(img1, img2, window, out);
}